// round 6
// baseline (speedup 1.0000x reference)
#include <cuda_runtime.h>
#include <cstdint>

#define BATCH 4096
#define MCOLS 4096
#define NROWS 4096
#define NNZ_PER_ROW 819
#define NNZ_TOTAL (NROWS * NNZ_PER_ROW)

#define BM 128
#define BN 128
#define BK 32
#define KSTEPS (MCOLS / BK)        // 128
#define NSTAGES 3
#define SROW 36                    // floats; conflict-free scalar LDS (4*qr+tg distinct mod 32)
#define TILE_FLOATS (128 * SROW)   // 4608 floats per matrix per stage
#define STAGE_FLOATS (2 * TILE_FLOATS)            // A+B per stage = 9216 floats (36KB)
#define SMEM_BYTES (NSTAGES * STAGE_FLOATS * 4)   // 110592 B -> 2 CTAs/SM

// Pre-rounded tf32 operand buffers (plain row-major layout).
// g_Wdense is zero-initialized at module load; scatter writes the same values
// to the same (fixed CSR) positions every call -> deterministic across replays.
__device__ float g_Wdense[(size_t)NROWS * MCOLS];
__device__ float g_Xtf32[(size_t)BATCH * MCOLS];

__global__ void scatter_kernel(const float* __restrict__ val,
                               const int* __restrict__ rows,
                               const int* __restrict__ cols) {
    int i = blockIdx.x * blockDim.x + threadIdx.x;
    if (i < NNZ_TOTAL) {
        float v = val[i];
        uint32_t t;
        asm("cvt.rna.tf32.f32 %0, %1;" : "=r"(t) : "f"(v));
        g_Wdense[(size_t)rows[i] * MCOLS + cols[i]] = __uint_as_float(t);
    }
}

// Rounding-only copy of x into tf32 bits (layout unchanged).
__global__ void __launch_bounds__(256)
round_x_kernel(const float* __restrict__ x) {
    size_t i = (size_t)(blockIdx.x * blockDim.x + threadIdx.x) * 4;
    float4 v = *(const float4*)(x + i);
    uint32_t a, b, c, d;
    asm("cvt.rna.tf32.f32 %0, %1;" : "=r"(a) : "f"(v.x));
    asm("cvt.rna.tf32.f32 %0, %1;" : "=r"(b) : "f"(v.y));
    asm("cvt.rna.tf32.f32 %0, %1;" : "=r"(c) : "f"(v.z));
    asm("cvt.rna.tf32.f32 %0, %1;" : "=r"(d) : "f"(v.w));
    float4 o;
    o.x = __uint_as_float(a); o.y = __uint_as_float(b);
    o.z = __uint_as_float(c); o.w = __uint_as_float(d);
    *(float4*)(g_Xtf32 + i) = o;
}

__device__ __forceinline__ void cp16(uint32_t dst, const void* src) {
    asm volatile("cp.async.cg.shared.global [%0], [%1], 16;\n" :: "r"(dst), "l"(src));
}

__device__ __forceinline__ void load_stage(uint32_t sAt, uint32_t sBt,
                                           const float* __restrict__ gA,
                                           const float* __restrict__ gB) {
    #pragma unroll
    for (int i = 0; i < 4; ++i) {
        uint32_t so = (uint32_t)(i * 32 * SROW) * 4;   // +32 rows per step
        cp16(sAt + so, gA + (size_t)i * 32 * MCOLS);
        cp16(sBt + so, gB + (size_t)i * 32 * MCOLS);
    }
    asm volatile("cp.async.commit_group;\n" ::);
}

#define MMA(d, a0, a1, a2, a3, b0, b1)                                      \
    asm volatile(                                                           \
        "mma.sync.aligned.m16n8k8.row.col.f32.tf32.tf32.f32 "               \
        "{%0,%1,%2,%3}, {%4,%5,%6,%7}, {%8,%9}, {%0,%1,%2,%3};"             \
        : "+f"((d)[0]), "+f"((d)[1]), "+f"((d)[2]), "+f"((d)[3])            \
        : "r"(a0), "r"(a1), "r"(a2), "r"(a3), "r"(b0), "r"(b1))

__global__ void __launch_bounds__(256, 2)
sgemm_tf32(const float* __restrict__ bias, float* __restrict__ out) {
    extern __shared__ float smem[];

    const int tid  = threadIdx.x;
    const int lane = tid & 31;
    const int warp = tid >> 5;
    const int wm = (warp & 3) * 32;     // 4 warps in M
    const int wn = (warp >> 2) * 64;    // 2 warps in N
    const int qr = lane >> 2;
    const int tg = lane & 3;

    const int m0 = blockIdx.y * BM;
    const int n0 = blockIdx.x * BN;

    float acc[2][8][4];
    #pragma unroll
    for (int i = 0; i < 2; i++)
        #pragma unroll
        for (int j = 0; j < 8; j++)
            #pragma unroll
            for (int c = 0; c < 4; c++) acc[i][j][c] = 0.f;

    const uint32_t sbase = (uint32_t)__cvta_generic_to_shared(smem);

    // loader thread's fixed (row, seg)
    const int lrow = tid >> 3;          // 0..31
    const int lseg = tid & 7;           // 0..7 (16B chunks)
    const uint32_t lA = sbase + (uint32_t)(lrow * SROW + lseg * 4) * 4;
    const uint32_t lB = lA + (uint32_t)(TILE_FLOATS * 4);
    const float* gA = g_Xtf32 + (size_t)(m0 + lrow) * MCOLS + lseg * 4;
    const float* gB = g_Wdense + (size_t)(n0 + lrow) * MCOLS + lseg * 4;

    // prologue: stages 0 and 1
    load_stage(lA, lB, gA, gB);
    load_stage(lA + STAGE_FLOATS * 4, lB + STAGE_FLOATS * 4, gA + BK, gB + BK);

    for (int kt = 0; kt < KSTEPS; ++kt) {
        const int s = kt % NSTAGES;
        // Stage-kt completeness: at this point this thread has issued groups for
        // stages 0..kt+1; allowing 1 pending group = stage kt+1 only, so stage kt
        // is guaranteed landed.
        if (kt + 1 < KSTEPS) {
            asm volatile("cp.async.wait_group 1;\n" ::);
        } else {
            asm volatile("cp.async.wait_group 0;\n" ::);
        }
        __syncthreads();   // single barrier per ktile; also gates buffer reuse

        // issue stage kt+2 (overwrites buffer (kt-1)%3, whose readers finished
        // in iter kt-1, strictly before the barrier above)
        if (kt + 2 < KSTEPS) {
            const int b = (kt + 2) % NSTAGES;
            load_stage(lA + (uint32_t)(b * STAGE_FLOATS * 4),
                       lB + (uint32_t)(b * STAGE_FLOATS * 4),
                       gA + (size_t)(kt + 2) * BK, gB + (size_t)(kt + 2) * BK);
        }

        const float* Ac = smem + s * STAGE_FLOATS;
        const float* Bc = Ac + TILE_FLOATS;

        #pragma unroll
        for (int ks = 0; ks < 4; ++ks) {
            const int kk = ks * 8 + tg;

            uint32_t af[2][4];
            #pragma unroll
            for (int mt = 0; mt < 2; ++mt) {
                const float* p = Ac + (wm + mt * 16 + qr) * SROW + kk;
                af[mt][0] = __float_as_uint(p[0]);
                af[mt][1] = __float_as_uint(p[8 * SROW]);
                af[mt][2] = __float_as_uint(p[4]);
                af[mt][3] = __float_as_uint(p[8 * SROW + 4]);
            }

            uint32_t bf[8][2];
            #pragma unroll
            for (int nt = 0; nt < 8; ++nt) {
                const float* q = Bc + (wn + nt * 8 + qr) * SROW + kk;
                bf[nt][0] = __float_as_uint(q[0]);
                bf[nt][1] = __float_as_uint(q[4]);
            }

            #pragma unroll
            for (int mt = 0; mt < 2; ++mt)
                #pragma unroll
                for (int nt = 0; nt < 8; ++nt)
                    MMA(acc[mt][nt], af[mt][0], af[mt][1], af[mt][2], af[mt][3],
                        bf[nt][0], bf[nt][1]);
        }
    }

    // Epilogue
    #pragma unroll
    for (int mt = 0; mt < 2; ++mt) {
        const int rbase = m0 + wm + mt * 16 + qr;
        #pragma unroll
        for (int nt = 0; nt < 8; ++nt) {
            const int nbase = n0 + wn + nt * 8 + 2 * tg;
            const float b0 = bias[nbase];
            const float b1 = bias[nbase + 1];
            float2 v0 = make_float2(acc[mt][nt][0] + b0, acc[mt][nt][1] + b1);
            float2 v1 = make_float2(acc[mt][nt][2] + b0, acc[mt][nt][3] + b1);
            *(float2*)(out + (size_t)rbase * NROWS + nbase) = v0;
            *(float2*)(out + (size_t)(rbase + 8) * NROWS + nbase) = v1;
        }
    }
}

extern "C" void kernel_launch(void* const* d_in, const int* in_sizes, int n_in,
                              void* d_out, int out_size) {
    const float* x    = (const float*)d_in[0];
    const float* wval = (const float*)d_in[1];
    const float* bias = (const float*)d_in[2];
    const int*   rows = (const int*)d_in[3];
    const int*   cols = (const int*)d_in[4];
    float* out = (float*)d_out;

    scatter_kernel<<<(NNZ_TOTAL + 255) / 256, 256>>>(wval, rows, cols);
    round_x_kernel<<<(BATCH * MCOLS) / (256 * 4), 256>>>(x);

    cudaFuncSetAttribute(sgemm_tf32,
                         cudaFuncAttributeMaxDynamicSharedMemorySize, SMEM_BYTES);
    dim3 grid(NROWS / BN, BATCH / BM);
    sgemm_tf32<<<grid, 256, SMEM_BYTES>>>(bias, out);
}

// round 7
// speedup vs baseline: 1.5351x; 1.5351x over previous
#include <cuda_runtime.h>
#include <cstdint>

#define BATCH 4096
#define MCOLS 4096
#define NROWS 4096
#define NNZ_PER_ROW 819
#define NNZ_TOTAL (NROWS * NNZ_PER_ROW)

#define BM 128
#define BN 128
#define BK 32
#define KSTEPS (MCOLS / BK)        // 128
#define SROW 36                    // floats; conflict-free scalar LDS (4*qr+tg distinct mod 32)
#define TILE_FLOATS (128 * SROW)   // 4608 floats per matrix per stage
#define STAGE_FLOATS (2 * TILE_FLOATS)       // A+B per stage (36KB)
#define SMEM_BYTES (2 * STAGE_FLOATS * 4)    // double buffered = 73728 B (R1-identical)

// Pre-rounded tf32 operand buffers (plain row-major layout).
// g_Wdense is zero-initialized at module load; scatter writes the same values
// to the same (fixed CSR) positions every call -> deterministic across replays.
__device__ float g_Wdense[(size_t)NROWS * MCOLS];
__device__ float g_Xtf32[(size_t)BATCH * MCOLS];

__global__ void scatter_kernel(const float* __restrict__ val,
                               const int* __restrict__ rows,
                               const int* __restrict__ cols) {
    int i = blockIdx.x * blockDim.x + threadIdx.x;
    if (i < NNZ_TOTAL) {
        float v = val[i];
        uint32_t t;
        asm("cvt.rna.tf32.f32 %0, %1;" : "=r"(t) : "f"(v));
        g_Wdense[(size_t)rows[i] * MCOLS + cols[i]] = __uint_as_float(t);
    }
}

// Rounding-only copy of x into tf32 bits (layout unchanged).
__global__ void __launch_bounds__(256)
round_x_kernel(const float* __restrict__ x) {
    size_t i = (size_t)(blockIdx.x * blockDim.x + threadIdx.x) * 4;
    float4 v = *(const float4*)(x + i);
    uint32_t a, b, c, d;
    asm("cvt.rna.tf32.f32 %0, %1;" : "=r"(a) : "f"(v.x));
    asm("cvt.rna.tf32.f32 %0, %1;" : "=r"(b) : "f"(v.y));
    asm("cvt.rna.tf32.f32 %0, %1;" : "=r"(c) : "f"(v.z));
    asm("cvt.rna.tf32.f32 %0, %1;" : "=r"(d) : "f"(v.w));
    float4 o;
    o.x = __uint_as_float(a); o.y = __uint_as_float(b);
    o.z = __uint_as_float(c); o.w = __uint_as_float(d);
    *(float4*)(g_Xtf32 + i) = o;
}

__device__ __forceinline__ void cp16(uint32_t dst, const void* src) {
    asm volatile("cp.async.cg.shared.global [%0], [%1], 16;\n" :: "r"(dst), "l"(src));
}

__device__ __forceinline__ void load_stage(uint32_t sAt, uint32_t sBt,
                                           const float* __restrict__ gA,
                                           const float* __restrict__ gB) {
    #pragma unroll
    for (int i = 0; i < 4; ++i) {
        uint32_t so = (uint32_t)(i * 32 * SROW) * 4;   // +32 rows per step
        cp16(sAt + so, gA + (size_t)i * 32 * MCOLS);
        cp16(sBt + so, gB + (size_t)i * 32 * MCOLS);
    }
    asm volatile("cp.async.commit_group;\n" ::);
}

#define MMA(d, a0, a1, a2, a3, b0, b1)                                      \
    asm volatile(                                                           \
        "mma.sync.aligned.m16n8k8.row.col.f32.tf32.tf32.f32 "               \
        "{%0,%1,%2,%3}, {%4,%5,%6,%7}, {%8,%9}, {%0,%1,%2,%3};"             \
        : "+f"((d)[0]), "+f"((d)[1]), "+f"((d)[2]), "+f"((d)[3])            \
        : "r"(a0), "r"(a1), "r"(a2), "r"(a3), "r"(b0), "r"(b1))

__device__ __forceinline__ void load_frags(uint32_t af[2][4], uint32_t bf[8][2],
                                           const float* __restrict__ Ac,
                                           const float* __restrict__ Bc,
                                           int ks, int wm, int wn, int qr, int tg) {
    const int kk = ks * 8 + tg;
    #pragma unroll
    for (int mt = 0; mt < 2; ++mt) {
        const float* p = Ac + (wm + mt * 16 + qr) * SROW + kk;
        af[mt][0] = __float_as_uint(p[0]);
        af[mt][1] = __float_as_uint(p[8 * SROW]);
        af[mt][2] = __float_as_uint(p[4]);
        af[mt][3] = __float_as_uint(p[8 * SROW + 4]);
    }
    #pragma unroll
    for (int nt = 0; nt < 8; ++nt) {
        const float* q = Bc + (wn + nt * 8 + qr) * SROW + kk;
        bf[nt][0] = __float_as_uint(q[0]);
        bf[nt][1] = __float_as_uint(q[4]);
    }
}

__global__ void __launch_bounds__(256, 2)
sgemm_tf32(const float* __restrict__ bias, float* __restrict__ out) {
    extern __shared__ float smem[];

    const int tid  = threadIdx.x;
    const int lane = tid & 31;
    const int warp = tid >> 5;
    const int wm = (warp & 3) * 32;     // 4 warps in M
    const int wn = (warp >> 2) * 64;    // 2 warps in N
    const int qr = lane >> 2;
    const int tg = lane & 3;

    const int m0 = blockIdx.y * BM;
    const int n0 = blockIdx.x * BN;

    float acc[2][8][4];
    #pragma unroll
    for (int i = 0; i < 2; i++)
        #pragma unroll
        for (int j = 0; j < 8; j++)
            #pragma unroll
            for (int c = 0; c < 4; c++) acc[i][j][c] = 0.f;

    const uint32_t sbase = (uint32_t)__cvta_generic_to_shared(smem);

    // loader thread's fixed (row, seg)
    const int lrow = tid >> 3;          // 0..31
    const int lseg = tid & 7;           // 0..7 (16B chunks)
    const uint32_t lA = sbase + (uint32_t)(lrow * SROW + lseg * 4) * 4;
    const uint32_t lB = lA + (uint32_t)(TILE_FLOATS * 4);
    const float* gA = g_Xtf32 + (size_t)(m0 + lrow) * MCOLS + lseg * 4;
    const float* gB = g_Wdense + (size_t)(n0 + lrow) * MCOLS + lseg * 4;

    load_stage(lA, lB, gA, gB);

    for (int kt = 0; kt < KSTEPS; ++kt) {
        const int cur = kt & 1;
        if (kt + 1 < KSTEPS) {
            // prefetch next stage BEFORE the wait (R1-proven ordering)
            load_stage(lA + (uint32_t)((cur ^ 1) * STAGE_FLOATS * 4),
                       lB + (uint32_t)((cur ^ 1) * STAGE_FLOATS * 4),
                       gA + (size_t)(kt + 1) * BK, gB + (size_t)(kt + 1) * BK);
            asm volatile("cp.async.wait_group 1;\n" ::);
        } else {
            asm volatile("cp.async.wait_group 0;\n" ::);
        }
        __syncthreads();

        const float* Ac = smem + cur * STAGE_FLOATS;
        const float* Bc = Ac + TILE_FLOATS;

        // Cross-ks fragment pipeline: load ks+1 operands while ks MMAs issue.
        uint32_t af[2][2][4];
        uint32_t bf[2][8][2];
        load_frags(af[0], bf[0], Ac, Bc, 0, wm, wn, qr, tg);

        #pragma unroll
        for (int ks = 0; ks < 4; ++ks) {
            const int c = ks & 1;
            if (ks < 3)
                load_frags(af[c ^ 1], bf[c ^ 1], Ac, Bc, ks + 1, wm, wn, qr, tg);
            #pragma unroll
            for (int mt = 0; mt < 2; ++mt)
                #pragma unroll
                for (int nt = 0; nt < 8; ++nt)
                    MMA(acc[mt][nt], af[c][mt][0], af[c][mt][1],
                        af[c][mt][2], af[c][mt][3],
                        bf[c][nt][0], bf[c][nt][1]);
        }
        __syncthreads();
    }

    // Epilogue
    #pragma unroll
    for (int mt = 0; mt < 2; ++mt) {
        const int rbase = m0 + wm + mt * 16 + qr;
        #pragma unroll
        for (int nt = 0; nt < 8; ++nt) {
            const int nbase = n0 + wn + nt * 8 + 2 * tg;
            const float b0 = bias[nbase];
            const float b1 = bias[nbase + 1];
            float2 v0 = make_float2(acc[mt][nt][0] + b0, acc[mt][nt][1] + b1);
            float2 v1 = make_float2(acc[mt][nt][2] + b0, acc[mt][nt][3] + b1);
            *(float2*)(out + (size_t)rbase * NROWS + nbase) = v0;
            *(float2*)(out + (size_t)(rbase + 8) * NROWS + nbase) = v1;
        }
    }
}

extern "C" void kernel_launch(void* const* d_in, const int* in_sizes, int n_in,
                              void* d_out, int out_size) {
    const float* x    = (const float*)d_in[0];
    const float* wval = (const float*)d_in[1];
    const float* bias = (const float*)d_in[2];
    const int*   rows = (const int*)d_in[3];
    const int*   cols = (const int*)d_in[4];
    float* out = (float*)d_out;

    scatter_kernel<<<(NNZ_TOTAL + 255) / 256, 256>>>(wval, rows, cols);
    round_x_kernel<<<(BATCH * MCOLS) / (256 * 4), 256>>>(x);

    cudaFuncSetAttribute(sgemm_tf32,
                         cudaFuncAttributeMaxDynamicSharedMemorySize, SMEM_BYTES);
    dim3 grid(NROWS / BN, BATCH / BM);
    sgemm_tf32<<<grid, 256, SMEM_BYTES>>>(bias, out);
}

// round 8
// speedup vs baseline: 1.5402x; 1.0033x over previous
#include <cuda_runtime.h>
#include <cstdint>

#define BATCH 4096
#define MCOLS 4096
#define NROWS 4096
#define NNZ_PER_ROW 819
#define NNZ_TOTAL (NROWS * NNZ_PER_ROW)

#define BM 128
#define BN 128
#define BK 32
#define KSTEPS (MCOLS / BK)        // 128
#define NSTAGES 3
#define SROW 36                    // floats; conflict-free scalar LDS (4*qr+tg distinct mod 32)
#define TILE_FLOATS (128 * SROW)   // 4608 floats per matrix per stage
#define STAGE_FLOATS (2 * TILE_FLOATS)            // A+B per stage (36KB)
#define SMEM_BYTES (NSTAGES * STAGE_FLOATS * 4)   // 110592 B -> 2 CTAs/SM

#define XCHUNKS (BATCH * MCOLS / 4)   // float4 chunks of x

// Pre-rounded tf32 operand buffers (plain row-major layout).
// g_Wdense is zero-initialized at module load; the prep kernel writes the same
// values to the same (fixed CSR) positions every call -> deterministic replays.
__device__ float g_Wdense[(size_t)NROWS * MCOLS];
__device__ float g_Xtf32[(size_t)BATCH * MCOLS];

// Fused pre-pass: lower indices tf32-round x (streaming), upper indices scatter
// W values (random writes). The two halves run concurrently across SMs.
__global__ void __launch_bounds__(256)
prep_kernel(const float* __restrict__ x, const float* __restrict__ val,
            const int* __restrict__ rows, const int* __restrict__ cols) {
    int i = blockIdx.x * blockDim.x + threadIdx.x;
    if (i < XCHUNKS) {
        size_t o = (size_t)i * 4;
        float4 v = *(const float4*)(x + o);
        uint32_t a, b, c, d;
        asm("cvt.rna.tf32.f32 %0, %1;" : "=r"(a) : "f"(v.x));
        asm("cvt.rna.tf32.f32 %0, %1;" : "=r"(b) : "f"(v.y));
        asm("cvt.rna.tf32.f32 %0, %1;" : "=r"(c) : "f"(v.z));
        asm("cvt.rna.tf32.f32 %0, %1;" : "=r"(d) : "f"(v.w));
        float4 t;
        t.x = __uint_as_float(a); t.y = __uint_as_float(b);
        t.z = __uint_as_float(c); t.w = __uint_as_float(d);
        *(float4*)(g_Xtf32 + o) = t;
    } else {
        int j = i - XCHUNKS;
        if (j < NNZ_TOTAL) {
            float v = val[j];
            uint32_t t;
            asm("cvt.rna.tf32.f32 %0, %1;" : "=r"(t) : "f"(v));
            g_Wdense[(size_t)rows[j] * MCOLS + cols[j]] = __uint_as_float(t);
        }
    }
}

__device__ __forceinline__ void cp16(uint32_t dst, const void* src) {
    asm volatile("cp.async.cg.shared.global [%0], [%1], 16;\n" :: "r"(dst), "l"(src));
}

__device__ __forceinline__ void load_stage(uint32_t sAt, uint32_t sBt,
                                           const float* __restrict__ gA,
                                           const float* __restrict__ gB) {
    #pragma unroll
    for (int i = 0; i < 4; ++i) {
        uint32_t so = (uint32_t)(i * 32 * SROW) * 4;   // +32 rows per step
        cp16(sAt + so, gA + (size_t)i * 32 * MCOLS);
        cp16(sBt + so, gB + (size_t)i * 32 * MCOLS);
    }
    asm volatile("cp.async.commit_group;\n" ::);
}

#define MMA(d, a0, a1, a2, a3, b0, b1)                                      \
    asm volatile(                                                           \
        "mma.sync.aligned.m16n8k8.row.col.f32.tf32.tf32.f32 "               \
        "{%0,%1,%2,%3}, {%4,%5,%6,%7}, {%8,%9}, {%0,%1,%2,%3};"             \
        : "+f"((d)[0]), "+f"((d)[1]), "+f"((d)[2]), "+f"((d)[3])            \
        : "r"(a0), "r"(a1), "r"(a2), "r"(a3), "r"(b0), "r"(b1))

__device__ __forceinline__ void load_frags(uint32_t af[2][4], uint32_t bf[8][2],
                                           const float* __restrict__ Ac,
                                           const float* __restrict__ Bc,
                                           int ks, int wm, int wn, int qr, int tg) {
    const int kk = ks * 8 + tg;
    #pragma unroll
    for (int mt = 0; mt < 2; ++mt) {
        const float* p = Ac + (wm + mt * 16 + qr) * SROW + kk;
        af[mt][0] = __float_as_uint(p[0]);
        af[mt][1] = __float_as_uint(p[8 * SROW]);
        af[mt][2] = __float_as_uint(p[4]);
        af[mt][3] = __float_as_uint(p[8 * SROW + 4]);
    }
    #pragma unroll
    for (int nt = 0; nt < 8; ++nt) {
        const float* q = Bc + (wn + nt * 8 + qr) * SROW + kk;
        bf[nt][0] = __float_as_uint(q[0]);
        bf[nt][1] = __float_as_uint(q[4]);
    }
}

__global__ void __launch_bounds__(256, 2)
sgemm_tf32(const float* __restrict__ bias, float* __restrict__ out) {
    extern __shared__ float smem[];

    const int tid  = threadIdx.x;
    const int lane = tid & 31;
    const int warp = tid >> 5;
    const int wm = (warp & 3) * 32;     // 4 warps in M
    const int wn = (warp >> 2) * 64;    // 2 warps in N
    const int qr = lane >> 2;
    const int tg = lane & 3;

    const int m0 = blockIdx.y * BM;
    const int n0 = blockIdx.x * BN;

    float acc[2][8][4];
    #pragma unroll
    for (int i = 0; i < 2; i++)
        #pragma unroll
        for (int j = 0; j < 8; j++)
            #pragma unroll
            for (int c = 0; c < 4; c++) acc[i][j][c] = 0.f;

    const uint32_t sbase = (uint32_t)__cvta_generic_to_shared(smem);

    // loader thread's fixed (row, seg)
    const int lrow = tid >> 3;          // 0..31
    const int lseg = tid & 7;           // 0..7 (16B chunks)
    const uint32_t lA = sbase + (uint32_t)(lrow * SROW + lseg * 4) * 4;
    const uint32_t lB = lA + (uint32_t)(TILE_FLOATS * 4);
    const float* gA = g_Xtf32 + (size_t)(m0 + lrow) * MCOLS + lseg * 4;
    const float* gB = g_Wdense + (size_t)(n0 + lrow) * MCOLS + lseg * 4;

    // prologue: stages 0 and 1 into buffers 0 and 1
    load_stage(lA, lB, gA, gB);
    load_stage(lA + STAGE_FLOATS * 4, lB + STAGE_FLOATS * 4, gA + BK, gB + BK);

    int cur = 0;   // buffer holding stage kt
    for (int kt = 0; kt < KSTEPS; ++kt) {
        // prefetch stage kt+2 into buffer (cur+2)%3 BEFORE the wait (R7 ordering).
        // That buffer was last read in iteration kt-1; the barrier at the end of
        // kt-1 makes this overwrite safe.
        if (kt + 2 < KSTEPS) {
            const int lb = (cur + 2 >= NSTAGES) ? cur - 1 : cur + 2;
            load_stage(lA + (uint32_t)(lb * STAGE_FLOATS * 4),
                       lB + (uint32_t)(lb * STAGE_FLOATS * 4),
                       gA + (size_t)(kt + 2) * BK, gB + (size_t)(kt + 2) * BK);
            asm volatile("cp.async.wait_group 2;\n" ::);   // stages kt+1, kt+2 may pend
        } else if (kt + 1 < KSTEPS) {
            asm volatile("cp.async.wait_group 1;\n" ::);   // stage kt+1 may pend
        } else {
            asm volatile("cp.async.wait_group 0;\n" ::);
        }
        __syncthreads();   // collective completion of stage kt

        const float* Ac = smem + cur * STAGE_FLOATS;
        const float* Bc = Ac + TILE_FLOATS;

        // Cross-ks fragment pipeline: load ks+1 operands while ks MMAs issue.
        uint32_t af[2][2][4];
        uint32_t bf[2][8][2];
        load_frags(af[0], bf[0], Ac, Bc, 0, wm, wn, qr, tg);

        #pragma unroll
        for (int ks = 0; ks < 4; ++ks) {
            const int c = ks & 1;
            if (ks < 3)
                load_frags(af[c ^ 1], bf[c ^ 1], Ac, Bc, ks + 1, wm, wn, qr, tg);
            #pragma unroll
            for (int mt = 0; mt < 2; ++mt)
                #pragma unroll
                for (int nt = 0; nt < 8; ++nt)
                    MMA(acc[mt][nt], af[c][mt][0], af[c][mt][1],
                        af[c][mt][2], af[c][mt][3],
                        bf[c][nt][0], bf[c][nt][1]);
        }
        __syncthreads();   // gate buffer reuse by next iteration's prefetch

        cur = (cur == NSTAGES - 1) ? 0 : cur + 1;
    }

    // Epilogue
    #pragma unroll
    for (int mt = 0; mt < 2; ++mt) {
        const int rbase = m0 + wm + mt * 16 + qr;
        #pragma unroll
        for (int nt = 0; nt < 8; ++nt) {
            const int nbase = n0 + wn + nt * 8 + 2 * tg;
            const float b0 = bias[nbase];
            const float b1 = bias[nbase + 1];
            float2 v0 = make_float2(acc[mt][nt][0] + b0, acc[mt][nt][1] + b1);
            float2 v1 = make_float2(acc[mt][nt][2] + b0, acc[mt][nt][3] + b1);
            *(float2*)(out + (size_t)rbase * NROWS + nbase) = v0;
            *(float2*)(out + (size_t)(rbase + 8) * NROWS + nbase) = v1;
        }
    }
}

extern "C" void kernel_launch(void* const* d_in, const int* in_sizes, int n_in,
                              void* d_out, int out_size) {
    const float* x    = (const float*)d_in[0];
    const float* wval = (const float*)d_in[1];
    const float* bias = (const float*)d_in[2];
    const int*   rows = (const int*)d_in[3];
    const int*   cols = (const int*)d_in[4];
    float* out = (float*)d_out;

    prep_kernel<<<(XCHUNKS + NNZ_TOTAL + 255) / 256, 256>>>(x, wval, rows, cols);

    cudaFuncSetAttribute(sgemm_tf32,
                         cudaFuncAttributeMaxDynamicSharedMemorySize, SMEM_BYTES);
    dim3 grid(NROWS / BN, BATCH / BM);
    sgemm_tf32<<<grid, 256, SMEM_BYTES>>>(bias, out);
}

// round 9
// speedup vs baseline: 2.5456x; 1.6528x over previous
#include <cuda_runtime.h>
#include <cuda_fp16.h>
#include <cstdint>

#define BATCH 4096
#define MCOLS 4096
#define NROWS 4096
#define NNZ_PER_ROW 819
#define NNZ_TOTAL (NROWS * NNZ_PER_ROW)

#define BM 128
#define BN 128
#define BK 32
#define KSTEPS (MCOLS / BK)        // 128
#define NSTAGES 3
#define SROWH 40                   // halves per row (80B); word = 20*qr + tg distinct mod 32
#define TILE_HALVES (128 * SROWH)  // 5120 halves (10KB) per matrix per stage
#define STAGE_HALVES (2 * TILE_HALVES)            // A+B per stage (20KB)
#define SMEM_BYTES (NSTAGES * STAGE_HALVES * 2)   // 61440 B

#define XCHUNKS (BATCH * MCOLS / 4)   // float4 chunks of x

// fp16 operand buffers. g_Wh is zero-initialized at module load (0 bits = +0.0h);
// the prep kernel writes the same values to the same (fixed CSR) positions every
// call -> deterministic across graph replays.
__device__ __half g_Wh[(size_t)NROWS * MCOLS];
__device__ __half g_Xh[(size_t)BATCH * MCOLS];

// Fused pre-pass: lower indices convert x -> fp16 (streaming), upper indices
// scatter W values as fp16 (random writes). Halves run concurrently across SMs.
__global__ void __launch_bounds__(256)
prep_kernel(const float* __restrict__ x, const float* __restrict__ val,
            const int* __restrict__ rows, const int* __restrict__ cols) {
    int i = blockIdx.x * blockDim.x + threadIdx.x;
    if (i < XCHUNKS) {
        size_t o = (size_t)i * 4;
        float4 v = *(const float4*)(x + o);
        __half2 h0 = __floats2half2_rn(v.x, v.y);
        __half2 h1 = __floats2half2_rn(v.z, v.w);
        uint2 p;
        p.x = *(const uint32_t*)&h0;
        p.y = *(const uint32_t*)&h1;
        *(uint2*)(g_Xh + o) = p;
    } else {
        int j = i - XCHUNKS;
        if (j < NNZ_TOTAL) {
            g_Wh[(size_t)rows[j] * MCOLS + cols[j]] = __float2half_rn(val[j]);
        }
    }
}

__device__ __forceinline__ void cp16(uint32_t dst, const void* src) {
    asm volatile("cp.async.cg.shared.global [%0], [%1], 16;\n" :: "r"(dst), "l"(src));
}

// Each thread owns 2 (row, seg) chunks per matrix: rows lrow and lrow+64.
__device__ __forceinline__ void load_stage(uint32_t sAt, uint32_t sBt,
                                           const __half* __restrict__ gA,
                                           const __half* __restrict__ gB) {
    #pragma unroll
    for (int i = 0; i < 2; ++i) {
        uint32_t so = (uint32_t)(i * 64 * SROWH) * 2;   // +64 rows per step
        cp16(sAt + so, gA + (size_t)i * 64 * MCOLS);
        cp16(sBt + so, gB + (size_t)i * 64 * MCOLS);
    }
    asm volatile("cp.async.commit_group;\n" ::);
}

#define MMA(d, a0, a1, a2, a3, b0, b1)                                      \
    asm volatile(                                                           \
        "mma.sync.aligned.m16n8k16.row.col.f32.f16.f16.f32 "                \
        "{%0,%1,%2,%3}, {%4,%5,%6,%7}, {%8,%9}, {%0,%1,%2,%3};"             \
        : "+f"((d)[0]), "+f"((d)[1]), "+f"((d)[2]), "+f"((d)[3])            \
        : "r"(a0), "r"(a1), "r"(a2), "r"(a3), "r"(b0), "r"(b1))

// fp16 m16n8k16 fragments (per ks-half of the 32-wide k-tile):
//   A: a0={row qr,   k 2tg..+1}  a1={row qr+8, k 2tg..+1}
//      a2={row qr,   k 2tg+8..+9} a3={row qr+8, k 2tg+8..+9}
//   B: b0={col qr, k 2tg..+1}    b1={col qr, k 2tg+8..+9}
__device__ __forceinline__ void load_frags(uint32_t af[2][4], uint32_t bf[8][2],
                                           const __half* __restrict__ Ac,
                                           const __half* __restrict__ Bc,
                                           int ks, int wm, int wn, int qr, int tg) {
    const int kk = ks * 16 + tg * 2;
    #pragma unroll
    for (int mt = 0; mt < 2; ++mt) {
        const __half* p = Ac + (wm + mt * 16 + qr) * SROWH + kk;
        af[mt][0] = *(const uint32_t*)(p);
        af[mt][1] = *(const uint32_t*)(p + 8 * SROWH);
        af[mt][2] = *(const uint32_t*)(p + 8);
        af[mt][3] = *(const uint32_t*)(p + 8 * SROWH + 8);
    }
    #pragma unroll
    for (int nt = 0; nt < 8; ++nt) {
        const __half* q = Bc + (wn + nt * 8 + qr) * SROWH + kk;
        bf[nt][0] = *(const uint32_t*)(q);
        bf[nt][1] = *(const uint32_t*)(q + 8);
    }
}

__global__ void __launch_bounds__(256, 2)
sgemm_fp16(const float* __restrict__ bias, float* __restrict__ out) {
    extern __shared__ __half smem[];

    const int tid  = threadIdx.x;
    const int lane = tid & 31;
    const int warp = tid >> 5;
    const int wm = (warp & 3) * 32;     // 4 warps in M
    const int wn = (warp >> 2) * 64;    // 2 warps in N
    const int qr = lane >> 2;
    const int tg = lane & 3;

    const int m0 = blockIdx.y * BM;
    const int n0 = blockIdx.x * BN;

    float acc[2][8][4];
    #pragma unroll
    for (int i = 0; i < 2; i++)
        #pragma unroll
        for (int j = 0; j < 8; j++)
            #pragma unroll
            for (int c = 0; c < 4; c++) acc[i][j][c] = 0.f;

    const uint32_t sbase = (uint32_t)__cvta_generic_to_shared(smem);

    // loader thread's fixed (row, seg): 4 chunks/row of 16B (32 halves)
    const int lrow = tid >> 2;          // 0..63
    const int lseg = tid & 3;           // 0..3
    const uint32_t lA = sbase + (uint32_t)(lrow * SROWH + lseg * 8) * 2;
    const uint32_t lB = lA + (uint32_t)(TILE_HALVES * 2);
    const __half* gA = g_Xh + (size_t)(m0 + lrow) * MCOLS + lseg * 8;
    const __half* gB = g_Wh + (size_t)(n0 + lrow) * MCOLS + lseg * 8;

    // prologue: stages 0 and 1 into buffers 0 and 1
    load_stage(lA, lB, gA, gB);
    load_stage(lA + STAGE_HALVES * 2, lB + STAGE_HALVES * 2, gA + BK, gB + BK);

    int cur = 0;   // buffer holding stage kt
    for (int kt = 0; kt < KSTEPS; ++kt) {
        // prefetch stage kt+2 BEFORE the wait (R7/R8-proven ordering); the
        // target buffer was last read in iteration kt-1, whose closing barrier
        // makes the overwrite safe.
        if (kt + 2 < KSTEPS) {
            const int lb = (cur + 2 >= NSTAGES) ? cur - 1 : cur + 2;
            load_stage(lA + (uint32_t)(lb * STAGE_HALVES * 2),
                       lB + (uint32_t)(lb * STAGE_HALVES * 2),
                       gA + (size_t)(kt + 2) * BK, gB + (size_t)(kt + 2) * BK);
            asm volatile("cp.async.wait_group 2;\n" ::);
        } else if (kt + 1 < KSTEPS) {
            asm volatile("cp.async.wait_group 1;\n" ::);
        } else {
            asm volatile("cp.async.wait_group 0;\n" ::);
        }
        __syncthreads();   // collective completion of stage kt

        const __half* Ac = smem + cur * STAGE_HALVES;
        const __half* Bc = Ac + TILE_HALVES;

        // Cross-ks fragment pipeline: load ks+1 operands while ks MMAs issue.
        uint32_t af[2][2][4];
        uint32_t bf[2][8][2];
        load_frags(af[0], bf[0], Ac, Bc, 0, wm, wn, qr, tg);

        #pragma unroll
        for (int ks = 0; ks < 2; ++ks) {
            const int c = ks & 1;
            if (ks < 1)
                load_frags(af[c ^ 1], bf[c ^ 1], Ac, Bc, ks + 1, wm, wn, qr, tg);
            #pragma unroll
            for (int mt = 0; mt < 2; ++mt)
                #pragma unroll
                for (int nt = 0; nt < 8; ++nt)
                    MMA(acc[mt][nt], af[c][mt][0], af[c][mt][1],
                        af[c][mt][2], af[c][mt][3],
                        bf[c][nt][0], bf[c][nt][1]);
        }
        __syncthreads();   // gate buffer reuse by next iteration's prefetch

        cur = (cur == NSTAGES - 1) ? 0 : cur + 1;
    }

    // Epilogue
    #pragma unroll
    for (int mt = 0; mt < 2; ++mt) {
        const int rbase = m0 + wm + mt * 16 + qr;
        #pragma unroll
        for (int nt = 0; nt < 8; ++nt) {
            const int nbase = n0 + wn + nt * 8 + 2 * tg;
            const float b0 = bias[nbase];
            const float b1 = bias[nbase + 1];
            float2 v0 = make_float2(acc[mt][nt][0] + b0, acc[mt][nt][1] + b1);
            float2 v1 = make_float2(acc[mt][nt][2] + b0, acc[mt][nt][3] + b1);
            *(float2*)(out + (size_t)rbase * NROWS + nbase) = v0;
            *(float2*)(out + (size_t)(rbase + 8) * NROWS + nbase) = v1;
        }
    }
}

extern "C" void kernel_launch(void* const* d_in, const int* in_sizes, int n_in,
                              void* d_out, int out_size) {
    const float* x    = (const float*)d_in[0];
    const float* wval = (const float*)d_in[1];
    const float* bias = (const float*)d_in[2];
    const int*   rows = (const int*)d_in[3];
    const int*   cols = (const int*)d_in[4];
    float* out = (float*)d_out;

    prep_kernel<<<(XCHUNKS + NNZ_TOTAL + 255) / 256, 256>>>(x, wval, rows, cols);

    cudaFuncSetAttribute(sgemm_fp16,
                         cudaFuncAttributeMaxDynamicSharedMemorySize, SMEM_BYTES);
    dim3 grid(NROWS / BN, BATCH / BM);
    sgemm_fp16<<<grid, 256, SMEM_BYTES>>>(bias, out);
}

// round 10
// speedup vs baseline: 2.7193x; 1.0682x over previous
#include <cuda_runtime.h>
#include <cuda_fp16.h>
#include <cstdint>

#define BATCH 4096
#define MCOLS 4096
#define NROWS 4096
#define NNZ_PER_ROW 819
#define NNZ_TOTAL (NROWS * NNZ_PER_ROW)

#define BM 128
#define BN 128
#define BK 32
#define KSTEPS (MCOLS / BK)        // 128
#define NSTAGES 3
#define SROWH 40                   // halves per row (80B); LDSM phases tile all 32 banks
#define TILE_HALVES (128 * SROWH)  // per matrix per stage (10KB)
#define STAGE_HALVES (2 * TILE_HALVES)            // A+B per stage (20KB)
#define SMEM_BYTES (NSTAGES * STAGE_HALVES * 2)   // 61440 B

#define XCHUNKS (BATCH * MCOLS / 4)   // float4 chunks of x

// fp16 operand buffers. g_Wh is zero-initialized at module load (0 bits = +0.0h);
// the prep kernel writes the same values to the same (fixed CSR) positions every
// call -> deterministic across graph replays.
__device__ __half g_Wh[(size_t)NROWS * MCOLS];
__device__ __half g_Xh[(size_t)BATCH * MCOLS];

__global__ void __launch_bounds__(256)
prep_kernel(const float* __restrict__ x, const float* __restrict__ val,
            const int* __restrict__ rows, const int* __restrict__ cols) {
    int i = blockIdx.x * blockDim.x + threadIdx.x;
    if (i < XCHUNKS) {
        size_t o = (size_t)i * 4;
        float4 v = *(const float4*)(x + o);
        __half2 h0 = __floats2half2_rn(v.x, v.y);
        __half2 h1 = __floats2half2_rn(v.z, v.w);
        uint2 p;
        p.x = *(const uint32_t*)&h0;
        p.y = *(const uint32_t*)&h1;
        *(uint2*)(g_Xh + o) = p;
    } else {
        int j = i - XCHUNKS;
        if (j < NNZ_TOTAL) {
            g_Wh[(size_t)rows[j] * MCOLS + cols[j]] = __float2half_rn(val[j]);
        }
    }
}

__device__ __forceinline__ void cp16(uint32_t dst, const void* src) {
    asm volatile("cp.async.cg.shared.global [%0], [%1], 16;\n" :: "r"(dst), "l"(src));
}

__device__ __forceinline__ void load_stage(uint32_t sAt, uint32_t sBt,
                                           const __half* __restrict__ gA,
                                           const __half* __restrict__ gB) {
    #pragma unroll
    for (int i = 0; i < 2; ++i) {
        uint32_t so = (uint32_t)(i * 64 * SROWH) * 2;   // +64 rows per step
        cp16(sAt + so, gA + (size_t)i * 64 * MCOLS);
        cp16(sBt + so, gB + (size_t)i * 64 * MCOLS);
    }
    asm volatile("cp.async.commit_group;\n" ::);
}

#define MMA(d, a0, a1, a2, a3, b0, b1)                                      \
    asm volatile(                                                           \
        "mma.sync.aligned.m16n8k16.row.col.f32.f16.f16.f32 "                \
        "{%0,%1,%2,%3}, {%4,%5,%6,%7}, {%8,%9}, {%0,%1,%2,%3};"             \
        : "+f"((d)[0]), "+f"((d)[1]), "+f"((d)[2]), "+f"((d)[3])            \
        : "r"(a0), "r"(a1), "r"(a2), "r"(a3), "r"(b0), "r"(b1))

#define LDSM4(r0, r1, r2, r3, addr)                                         \
    asm volatile("ldmatrix.sync.aligned.m8n8.x4.shared.b16 "                \
                 "{%0,%1,%2,%3}, [%4];"                                     \
                 : "=r"(r0), "=r"(r1), "=r"(r2), "=r"(r3) : "r"(addr))

// ldmatrix-based fragment loads.
// A x4 per (mt, ks): lanes 0-7 -> (rows wm+mt*16+l,   kh ks*16)    => a0
//                    lanes 8-15 -> (rows +8,          kh ks*16)    => a1
//                    lanes 16-23 -> (rows wm+mt*16+l, kh ks*16+8)  => a2
//                    lanes 24-31 -> (rows +8,         kh ks*16+8)  => a3
// B x4 per (ntp, ks) covers nt=2*ntp and 2*ntp+1:
//                    lanes 0-7   -> (n wn+nt*8+l,  kh ks*16)   => b[nt][0]
//                    lanes 8-15  -> (same n,       kh ks*16+8) => b[nt][1]
//                    lanes 16-23 -> (n +8,         kh ks*16)   => b[nt+1][0]
//                    lanes 24-31 -> (n +8,         kh ks*16+8) => b[nt+1][1]
__device__ __forceinline__ void load_frags(uint32_t af[2][4], uint32_t bf[8][2],
                                           uint32_t aAddr, uint32_t bAddr, int ks) {
    #pragma unroll
    for (int mt = 0; mt < 2; ++mt)
        LDSM4(af[mt][0], af[mt][1], af[mt][2], af[mt][3],
              aAddr + (uint32_t)((mt * 16 * SROWH + ks * 16) * 2));
    #pragma unroll
    for (int ntp = 0; ntp < 4; ++ntp)
        LDSM4(bf[2 * ntp][0], bf[2 * ntp][1], bf[2 * ntp + 1][0], bf[2 * ntp + 1][1],
              bAddr + (uint32_t)((ntp * 16 * SROWH + ks * 16) * 2));
}

__global__ void __launch_bounds__(256, 2)
sgemm_fp16(const float* __restrict__ bias, float* __restrict__ out) {
    extern __shared__ __half smem[];

    const int tid  = threadIdx.x;
    const int lane = tid & 31;
    const int warp = tid >> 5;
    const int wm = (warp & 3) * 32;     // 4 warps in M
    const int wn = (warp >> 2) * 64;    // 2 warps in N
    const int qr = lane >> 2;
    const int tg = lane & 3;

    const int m0 = blockIdx.y * BM;
    const int n0 = blockIdx.x * BN;

    float acc[2][8][4];
    #pragma unroll
    for (int i = 0; i < 2; i++)
        #pragma unroll
        for (int j = 0; j < 8; j++)
            #pragma unroll
            for (int c = 0; c < 4; c++) acc[i][j][c] = 0.f;

    const uint32_t sbase = (uint32_t)__cvta_generic_to_shared(smem);

    // ldmatrix per-lane source addresses (within stage 0; add stage offset later)
    const int lrA = wm + (lane & 7) + ((lane >> 3) & 1) * 8;
    const int lkA = (lane >> 4) * 8;
    const int lrB = wn + (lane & 7) + (lane >> 4) * 8;
    const int lkB = ((lane >> 3) & 1) * 8;
    const uint32_t aFrag0 = sbase + (uint32_t)((lrA * SROWH + lkA) * 2);
    const uint32_t bFrag0 = sbase + (uint32_t)(TILE_HALVES * 2)
                                  + (uint32_t)((lrB * SROWH + lkB) * 2);

    // loader thread's fixed (row, seg): 4 chunks/row of 16B (32 halves)
    const int lrow = tid >> 2;          // 0..63
    const int lseg = tid & 3;           // 0..3
    const uint32_t lA = sbase + (uint32_t)(lrow * SROWH + lseg * 8) * 2;
    const uint32_t lB = lA + (uint32_t)(TILE_HALVES * 2);
    const __half* gA = g_Xh + (size_t)(m0 + lrow) * MCOLS + lseg * 8;
    const __half* gB = g_Wh + (size_t)(n0 + lrow) * MCOLS + lseg * 8;

    // prologue: stages 0 and 1 into buffers 0 and 1
    load_stage(lA, lB, gA, gB);
    load_stage(lA + STAGE_HALVES * 2, lB + STAGE_HALVES * 2, gA + BK, gB + BK);

    int cur = 0;   // buffer holding stage kt
    for (int kt = 0; kt < KSTEPS; ++kt) {
        if (kt + 2 < KSTEPS) {
            const int lb = (cur + 2 >= NSTAGES) ? cur - 1 : cur + 2;
            load_stage(lA + (uint32_t)(lb * STAGE_HALVES * 2),
                       lB + (uint32_t)(lb * STAGE_HALVES * 2),
                       gA + (size_t)(kt + 2) * BK, gB + (size_t)(kt + 2) * BK);
            asm volatile("cp.async.wait_group 2;\n" ::);
        } else if (kt + 1 < KSTEPS) {
            asm volatile("cp.async.wait_group 1;\n" ::);
        } else {
            asm volatile("cp.async.wait_group 0;\n" ::);
        }
        __syncthreads();   // collective completion of stage kt

        const uint32_t aAddr = aFrag0 + (uint32_t)(cur * STAGE_HALVES * 2);
        const uint32_t bAddr = bFrag0 + (uint32_t)(cur * STAGE_HALVES * 2);

        // Cross-ks fragment pipeline: load ks+1 operands while ks MMAs issue.
        uint32_t af[2][2][4];
        uint32_t bf[2][8][2];
        load_frags(af[0], bf[0], aAddr, bAddr, 0);

        #pragma unroll
        for (int ks = 0; ks < 2; ++ks) {
            const int c = ks & 1;
            if (ks < 1)
                load_frags(af[c ^ 1], bf[c ^ 1], aAddr, bAddr, ks + 1);
            #pragma unroll
            for (int mt = 0; mt < 2; ++mt)
                #pragma unroll
                for (int nt = 0; nt < 8; ++nt)
                    MMA(acc[mt][nt], af[c][mt][0], af[c][mt][1],
                        af[c][mt][2], af[c][mt][3],
                        bf[c][nt][0], bf[c][nt][1]);
        }
        __syncthreads();   // gate buffer reuse by next iteration's prefetch

        cur = (cur == NSTAGES - 1) ? 0 : cur + 1;
    }

    // Epilogue
    #pragma unroll
    for (int mt = 0; mt < 2; ++mt) {
        const int rbase = m0 + wm + mt * 16 + qr;
        #pragma unroll
        for (int nt = 0; nt < 8; ++nt) {
            const int nbase = n0 + wn + nt * 8 + 2 * tg;
            const float b0 = bias[nbase];
            const float b1 = bias[nbase + 1];
            float2 v0 = make_float2(acc[mt][nt][0] + b0, acc[mt][nt][1] + b1);
            float2 v1 = make_float2(acc[mt][nt][2] + b0, acc[mt][nt][3] + b1);
            *(float2*)(out + (size_t)rbase * NROWS + nbase) = v0;
            *(float2*)(out + (size_t)(rbase + 8) * NROWS + nbase) = v1;
        }
    }
}

extern "C" void kernel_launch(void* const* d_in, const int* in_sizes, int n_in,
                              void* d_out, int out_size) {
    const float* x    = (const float*)d_in[0];
    const float* wval = (const float*)d_in[1];
    const float* bias = (const float*)d_in[2];
    const int*   rows = (const int*)d_in[3];
    const int*   cols = (const int*)d_in[4];
    float* out = (float*)d_out;

    prep_kernel<<<(XCHUNKS + NNZ_TOTAL + 255) / 256, 256>>>(x, wval, rows, cols);

    cudaFuncSetAttribute(sgemm_fp16,
                         cudaFuncAttributeMaxDynamicSharedMemorySize, SMEM_BYTES);
    dim3 grid(NROWS / BN, BATCH / BM);
    sgemm_fp16<<<grid, 256, SMEM_BYTES>>>(bias, out);
}